// round 1
// baseline (speedup 1.0000x reference)
#include <cuda_runtime.h>
#include <math.h>

#define T_SEQ   2048
#define NH      16
#define HD      64
#define DM      1024
#define BATCH   2
#define MROWS   (BATCH * T_SEQ)   // 4096

// Scratch (device globals: allocation-free per harness rules)
__device__ float g_Q[(size_t)BATCH * NH * T_SEQ * HD];
__device__ float g_K[(size_t)BATCH * NH * T_SEQ * HD];
__device__ float g_V[(size_t)BATCH * NH * T_SEQ * HD];
__device__ float g_O[(size_t)BATCH * NH * T_SEQ * HD];
__device__ float g_Y[(size_t)MROWS * DM];

// ---------------------------------------------------------------------------
// GEMM: C[m,n] = sum_k A[m,k] * B[n,k]   (both row-major, K contiguous = "NT")
// layout 0: C row-major (M x N).  layout 1: C scattered to (B,H,T,D).
// Block 128x128, K-tile 8, 256 threads, 8x8 register tile per thread.
// ---------------------------------------------------------------------------
#define BM 128
#define BN 128
#define BK 8

__global__ __launch_bounds__(256) void gemm_nt(
    const float* __restrict__ A, const float* __restrict__ B,
    float* __restrict__ C, int M, int N, int K, int layout)
{
    __shared__ __align__(16) float As[BK][BM];
    __shared__ __align__(16) float Bs[BK][BN];

    const int tid = threadIdx.x;
    const int bm = blockIdx.y;
    const int bn = blockIdx.x;

    const int rowBase = (tid >> 4) * 8;   // 0..120
    const int colBase = (tid & 15) * 8;   // 0..120

    const int la_row = tid >> 1;          // 0..127
    const int la_k4  = (tid & 1) * 4;     // 0 or 4

    const float* Ag = A + (size_t)(bm * BM + la_row) * K + la_k4;
    const float* Bg = B + (size_t)(bn * BN + la_row) * K + la_k4;

    float acc[8][8];
#pragma unroll
    for (int i = 0; i < 8; i++)
#pragma unroll
        for (int j = 0; j < 8; j++) acc[i][j] = 0.f;

    float4 av = *(const float4*)(Ag);
    float4 bv = *(const float4*)(Bg);

    for (int kt = 0; kt < K; kt += BK) {
        __syncthreads();
        As[la_k4 + 0][la_row] = av.x;
        As[la_k4 + 1][la_row] = av.y;
        As[la_k4 + 2][la_row] = av.z;
        As[la_k4 + 3][la_row] = av.w;
        Bs[la_k4 + 0][la_row] = bv.x;
        Bs[la_k4 + 1][la_row] = bv.y;
        Bs[la_k4 + 2][la_row] = bv.z;
        Bs[la_k4 + 3][la_row] = bv.w;
        __syncthreads();

        if (kt + BK < K) {
            av = *(const float4*)(Ag + kt + BK);
            bv = *(const float4*)(Bg + kt + BK);
        }

#pragma unroll
        for (int k = 0; k < BK; k++) {
            float4 a0 = *(const float4*)&As[k][rowBase];
            float4 a1 = *(const float4*)&As[k][rowBase + 4];
            float4 b0 = *(const float4*)&Bs[k][colBase];
            float4 b1 = *(const float4*)&Bs[k][colBase + 4];
            float ar[8] = {a0.x, a0.y, a0.z, a0.w, a1.x, a1.y, a1.z, a1.w};
            float br[8] = {b0.x, b0.y, b0.z, b0.w, b1.x, b1.y, b1.z, b1.w};
#pragma unroll
            for (int i = 0; i < 8; i++)
#pragma unroll
                for (int j = 0; j < 8; j++)
                    acc[i][j] += ar[i] * br[j];
        }
    }

    if (layout == 0) {
#pragma unroll
        for (int i = 0; i < 8; i++) {
            float* p = C + (size_t)(bm * BM + rowBase + i) * N + bn * BN + colBase;
            float4 v0 = {acc[i][0], acc[i][1], acc[i][2], acc[i][3]};
            float4 v1 = {acc[i][4], acc[i][5], acc[i][6], acc[i][7]};
            *(float4*)(p)     = v0;
            *(float4*)(p + 4) = v1;
        }
    } else {
        // n = h*64 + d ; m = b*T + t ; out[((b*NH+h)*T + t)*HD + d]
        const int n0 = bn * BN + colBase;
        const int h  = n0 >> 6;
        const int d  = n0 & 63;   // 8 cols stay inside one head (64 % 8 == 0)
#pragma unroll
        for (int i = 0; i < 8; i++) {
            const int m = bm * BM + rowBase + i;
            const int b = m >> 11;        // /2048
            const int t = m & 2047;
            float* p = C + (((size_t)(b * NH + h) * T_SEQ + t) * HD + d);
            float4 v0 = {acc[i][0], acc[i][1], acc[i][2], acc[i][3]};
            float4 v1 = {acc[i][4], acc[i][5], acc[i][6], acc[i][7]};
            *(float4*)(p)     = v0;
            *(float4*)(p + 4) = v1;
        }
    }
}

// ---------------------------------------------------------------------------
// Retention attention (quadratic, causal, decay-masked), flash-style tiles.
// grid = (T/64, B*H), 256 threads. Dynamic smem: Qs|Kt|Vs|Ss each 64x64 f32.
// O[b,h,i,:] = sum_{j<=i} gamma_h^(i-j) * (q_i . k_j) / 8 * v_j
// ---------------------------------------------------------------------------
__global__ __launch_bounds__(256) void retention_attn(
    const float* __restrict__ Q, const float* __restrict__ K,
    const float* __restrict__ V, float* __restrict__ O)
{
    extern __shared__ __align__(16) float sm[];
    float* Qs = sm;                 // [t][d] 64x64
    float* Kt = sm + 4096;          // [d][t] 64x64 (transposed)
    float* Vs = sm + 8192;          // [t][d] 64x64
    float* Ss = sm + 12288;         // [ti][tj] 64x64

    const int bh = blockIdx.y;
    const int h  = bh & (NH - 1);
    const int r0 = blockIdx.x * 64;
    const int tid = threadIdx.x;
    const int rB = (tid >> 4) * 4;   // 0..60
    const int cB = (tid & 15) * 4;   // 0..60

    // gamma in double so the up-to-2048 power stays accurate
    const double g_d = 1.0 - exp2(-5.0 - 0.5 * (double)h);
    const float lg = (float)log2(g_d);   // log2(gamma) < 0

    // load Q tile
    const float* Qg = Q + ((size_t)bh * T_SEQ + r0) * HD;
#pragma unroll
    for (int u = 0; u < 4; u++) {
        int idx = tid + u * 256;       // float4 index 0..1023
        int t = idx >> 4;
        int d4 = (idx & 15) * 4;
        *(float4*)&Qs[t * 64 + d4] = *(const float4*)(Qg + t * 64 + d4);
    }

    float acc[4][4];
#pragma unroll
    for (int i = 0; i < 4; i++)
#pragma unroll
        for (int j = 0; j < 4; j++) acc[i][j] = 0.f;

    for (int j0 = 0; j0 <= r0; j0 += 64) {
        __syncthreads();   // prev iter consumers done before overwrite
        const float* Kg = K + ((size_t)bh * T_SEQ + j0) * HD;
        const float* Vg = V + ((size_t)bh * T_SEQ + j0) * HD;
#pragma unroll
        for (int u = 0; u < 4; u++) {
            int idx = tid + u * 256;
            int t = idx >> 4;
            int d4 = (idx & 15) * 4;
            float4 kv = *(const float4*)(Kg + t * 64 + d4);
            Kt[(d4 + 0) * 64 + t] = kv.x;
            Kt[(d4 + 1) * 64 + t] = kv.y;
            Kt[(d4 + 2) * 64 + t] = kv.z;
            Kt[(d4 + 3) * 64 + t] = kv.w;
            *(float4*)&Vs[t * 64 + d4] = *(const float4*)(Vg + t * 64 + d4);
        }
        __syncthreads();

        // S = Q Kt  (inner over d)
        float s[4][4];
#pragma unroll
        for (int i = 0; i < 4; i++)
#pragma unroll
            for (int j = 0; j < 4; j++) s[i][j] = 0.f;

#pragma unroll 4
        for (int k = 0; k < 64; k++) {
            float a0 = Qs[(rB + 0) * 64 + k];
            float a1 = Qs[(rB + 1) * 64 + k];
            float a2 = Qs[(rB + 2) * 64 + k];
            float a3 = Qs[(rB + 3) * 64 + k];
            float4 bq = *(const float4*)&Kt[k * 64 + cB];
            s[0][0] += a0 * bq.x; s[0][1] += a0 * bq.y; s[0][2] += a0 * bq.z; s[0][3] += a0 * bq.w;
            s[1][0] += a1 * bq.x; s[1][1] += a1 * bq.y; s[1][2] += a1 * bq.z; s[1][3] += a1 * bq.w;
            s[2][0] += a2 * bq.x; s[2][1] += a2 * bq.y; s[2][2] += a2 * bq.z; s[2][3] += a2 * bq.w;
            s[3][0] += a3 * bq.x; s[3][1] += a3 * bq.y; s[3][2] += a3 * bq.z; s[3][3] += a3 * bq.w;
        }

        const bool diag = (j0 == r0);
#pragma unroll
        for (int i = 0; i < 4; i++) {
#pragma unroll
            for (int j = 0; j < 4; j++) {
                int di = (r0 + rB + i) - (j0 + cB + j);
                float dec = (!diag || di >= 0) ? exp2f((float)di * lg) : 0.f;
                Ss[(rB + i) * 64 + (cB + j)] = s[i][j] * 0.125f * dec;
            }
        }
        __syncthreads();

        // O += Ss @ Vs  (inner over key index)
#pragma unroll 4
        for (int k = 0; k < 64; k++) {
            float a0 = Ss[(rB + 0) * 64 + k];
            float a1 = Ss[(rB + 1) * 64 + k];
            float a2 = Ss[(rB + 2) * 64 + k];
            float a3 = Ss[(rB + 3) * 64 + k];
            float4 bv = *(const float4*)&Vs[k * 64 + cB];
            acc[0][0] += a0 * bv.x; acc[0][1] += a0 * bv.y; acc[0][2] += a0 * bv.z; acc[0][3] += a0 * bv.w;
            acc[1][0] += a1 * bv.x; acc[1][1] += a1 * bv.y; acc[1][2] += a1 * bv.z; acc[1][3] += a1 * bv.w;
            acc[2][0] += a2 * bv.x; acc[2][1] += a2 * bv.y; acc[2][2] += a2 * bv.z; acc[2][3] += a2 * bv.w;
            acc[3][0] += a3 * bv.x; acc[3][1] += a3 * bv.y; acc[3][2] += a3 * bv.z; acc[3][3] += a3 * bv.w;
        }
    }

    float* Og = O + ((size_t)bh * T_SEQ + r0) * HD;
#pragma unroll
    for (int i = 0; i < 4; i++) {
        float4 v = {acc[i][0], acc[i][1], acc[i][2], acc[i][3]};
        *(float4*)&Og[(rB + i) * 64 + cB] = v;
    }
}

// ---------------------------------------------------------------------------
// GroupNorm over (head_dim, T) per (b, h), then scatter to (B, T, C).
// grid = B*H blocks, 256 threads.
// ---------------------------------------------------------------------------
__global__ __launch_bounds__(256) void groupnorm_kernel(
    const float* __restrict__ O, const float* __restrict__ gw,
    const float* __restrict__ gb, float* __restrict__ Y)
{
    const int bh = blockIdx.x;
    const int h  = bh & (NH - 1);
    const int b  = bh >> 4;
    const int N  = T_SEQ * HD;   // 131072
    const float* Og = O + (size_t)bh * N;
    const int tid = threadIdx.x;

    double s = 0.0, s2 = 0.0;
    for (int i = tid; i < N; i += 256) {
        float v = Og[i];
        s  += (double)v;
        s2 += (double)v * (double)v;
    }
    __shared__ double sh[256], sh2[256];
    sh[tid] = s; sh2[tid] = s2;
    __syncthreads();
    for (int off = 128; off > 0; off >>= 1) {
        if (tid < off) { sh[tid] += sh[tid + off]; sh2[tid] += sh2[tid + off]; }
        __syncthreads();
    }
    __shared__ float mu_s, rs_s;
    if (tid == 0) {
        double mu  = sh[0] / N;
        double var = sh2[0] / N - mu * mu;
        mu_s = (float)mu;
        rs_s = (float)rsqrt(var + 1e-5);
    }
    __syncthreads();
    const float mu = mu_s, rs = rs_s;

    for (int i = tid; i < N; i += 256) {
        int t = i >> 6;
        int d = i & 63;
        float v = (Og[i] - mu) * rs * gw[h * HD + d] + gb[h * HD + d];
        Y[((size_t)b * T_SEQ + t) * DM + h * HD + d] = v;
    }
}

// ---------------------------------------------------------------------------
extern "C" void kernel_launch(void* const* d_in, const int* in_sizes, int n_in,
                              void* d_out, int out_size)
{
    const float* x   = (const float*)d_in[0];
    const float* Wq  = (const float*)d_in[1];
    const float* Wk  = (const float*)d_in[2];
    const float* Wv  = (const float*)d_in[3];
    const float* Wo  = (const float*)d_in[4];
    const float* gnw = (const float*)d_in[5];
    const float* gnb = (const float*)d_in[6];
    float* out = (float*)d_out;

    float *q, *k, *v, *o, *y;
    cudaGetSymbolAddress((void**)&q, g_Q);
    cudaGetSymbolAddress((void**)&k, g_K);
    cudaGetSymbolAddress((void**)&v, g_V);
    cudaGetSymbolAddress((void**)&o, g_O);
    cudaGetSymbolAddress((void**)&y, g_Y);

    dim3 gB(DM / BN, MROWS / BM);   // (8, 32)
    gemm_nt<<<gB, 256>>>(x, Wq, q, MROWS, DM, DM, 1);
    gemm_nt<<<gB, 256>>>(x, Wk, k, MROWS, DM, DM, 1);
    gemm_nt<<<gB, 256>>>(x, Wv, v, MROWS, DM, DM, 1);

    cudaFuncSetAttribute(retention_attn,
                         cudaFuncAttributeMaxDynamicSharedMemorySize, 65536);
    retention_attn<<<dim3(T_SEQ / 64, BATCH * NH), 256, 65536>>>(q, k, v, o);

    groupnorm_kernel<<<BATCH * NH, 256>>>(o, gnw, gnb, y);

    gemm_nt<<<gB, 256>>>(y, Wo, out, MROWS, DM, DM, 0);
}

// round 3
// speedup vs baseline: 1.7529x; 1.7529x over previous
#include <cuda_runtime.h>
#include <math.h>

#define T_SEQ   2048
#define NH      16
#define HD      64
#define DM      1024
#define BATCH   2
#define MROWS   (BATCH * T_SEQ)   // 4096
#define L_CH    64
#define NCH     (T_SEQ / L_CH)    // 32
#define BH      (BATCH * NH)      // 32

// Scratch (device globals: allocation-free per harness rules)
__device__ float g_Q[(size_t)BH * T_SEQ * HD];
__device__ float g_K[(size_t)BH * T_SEQ * HD];
__device__ float g_V[(size_t)BH * T_SEQ * HD];
__device__ float g_O[(size_t)BH * T_SEQ * HD];
__device__ float g_Y[(size_t)MROWS * DM];
__device__ float g_G[(size_t)BH * NCH * HD * HD];   // chunk contributions
__device__ float g_S[(size_t)BH * NCH * HD * HD];   // prefix states
__device__ double g_PS[BH * 16];
__device__ double g_PS2[BH * 16];
__device__ float g_MU[BH];
__device__ float g_RS[BH];

// ---------------------------------------------------------------------------
// GEMM: C[m,n] = sum_k A[m,k] * B[n,k]   (row-major, "NT")
// layout 0: C row-major.  layout 1: C scattered to (B,H,T,D).
// ---------------------------------------------------------------------------
#define BM 128
#define BN 128
#define BK 8

__global__ __launch_bounds__(256) void gemm_nt(
    const float* __restrict__ A, const float* __restrict__ B,
    float* __restrict__ C, int M, int N, int K, int layout)
{
    __shared__ __align__(16) float As[BK][BM];
    __shared__ __align__(16) float Bs[BK][BN];

    const int tid = threadIdx.x;
    const int bm = blockIdx.y;
    const int bn = blockIdx.x;

    const int rowBase = (tid >> 4) * 8;
    const int colBase = (tid & 15) * 8;

    const int la_row = tid >> 1;
    const int la_k4  = (tid & 1) * 4;

    const float* Ag = A + (size_t)(bm * BM + la_row) * K + la_k4;
    const float* Bg = B + (size_t)(bn * BN + la_row) * K + la_k4;

    float acc[8][8];
#pragma unroll
    for (int i = 0; i < 8; i++)
#pragma unroll
        for (int j = 0; j < 8; j++) acc[i][j] = 0.f;

    float4 av = *(const float4*)(Ag);
    float4 bv = *(const float4*)(Bg);

    for (int kt = 0; kt < K; kt += BK) {
        __syncthreads();
        As[la_k4 + 0][la_row] = av.x;
        As[la_k4 + 1][la_row] = av.y;
        As[la_k4 + 2][la_row] = av.z;
        As[la_k4 + 3][la_row] = av.w;
        Bs[la_k4 + 0][la_row] = bv.x;
        Bs[la_k4 + 1][la_row] = bv.y;
        Bs[la_k4 + 2][la_row] = bv.z;
        Bs[la_k4 + 3][la_row] = bv.w;
        __syncthreads();

        if (kt + BK < K) {
            av = *(const float4*)(Ag + kt + BK);
            bv = *(const float4*)(Bg + kt + BK);
        }

#pragma unroll
        for (int k = 0; k < BK; k++) {
            float4 a0 = *(const float4*)&As[k][rowBase];
            float4 a1 = *(const float4*)&As[k][rowBase + 4];
            float4 b0 = *(const float4*)&Bs[k][colBase];
            float4 b1 = *(const float4*)&Bs[k][colBase + 4];
            float ar[8] = {a0.x, a0.y, a0.z, a0.w, a1.x, a1.y, a1.z, a1.w};
            float br[8] = {b0.x, b0.y, b0.z, b0.w, b1.x, b1.y, b1.z, b1.w};
#pragma unroll
            for (int i = 0; i < 8; i++)
#pragma unroll
                for (int j = 0; j < 8; j++)
                    acc[i][j] += ar[i] * br[j];
        }
    }

    if (layout == 0) {
#pragma unroll
        for (int i = 0; i < 8; i++) {
            float* p = C + (size_t)(bm * BM + rowBase + i) * N + bn * BN + colBase;
            float4 v0 = {acc[i][0], acc[i][1], acc[i][2], acc[i][3]};
            float4 v1 = {acc[i][4], acc[i][5], acc[i][6], acc[i][7]};
            *(float4*)(p)     = v0;
            *(float4*)(p + 4) = v1;
        }
    } else {
        const int n0 = bn * BN + colBase;
        const int h  = n0 >> 6;
        const int d  = n0 & 63;
#pragma unroll
        for (int i = 0; i < 8; i++) {
            const int m = bm * BM + rowBase + i;
            const int b = m >> 11;
            const int t = m & 2047;
            float* p = C + (((size_t)(b * NH + h) * T_SEQ + t) * HD + d);
            float4 v0 = {acc[i][0], acc[i][1], acc[i][2], acc[i][3]};
            float4 v1 = {acc[i][4], acc[i][5], acc[i][6], acc[i][7]};
            *(float4*)(p)     = v0;
            *(float4*)(p + 4) = v1;
        }
    }
}

// ---------------------------------------------------------------------------
// Pass A: per-chunk state contribution  G_c[d1][d2] = sum_b gamma^(L-b) K[b][d1] V[b][d2]
// grid = (NCH, BH), 256 threads.
// ---------------------------------------------------------------------------
__global__ __launch_bounds__(256) void chunk_state(
    const float* __restrict__ K, const float* __restrict__ V,
    float* __restrict__ G)
{
    __shared__ __align__(16) float Ks[L_CH][HD];
    __shared__ __align__(16) float Vs[L_CH][HD];

    const int c  = blockIdx.x;
    const int bh = blockIdx.y;
    const int h  = bh & (NH - 1);
    const int tid = threadIdx.x;
    const int rB = (tid >> 4) * 4;
    const int cB = (tid & 15) * 4;

    const double g_d = 1.0 - exp2(-5.0 - 0.5 * (double)h);
    const float lg = (float)log2(g_d);

    const float* Kg = K + ((size_t)bh * T_SEQ + c * L_CH) * HD;
    const float* Vg = V + ((size_t)bh * T_SEQ + c * L_CH) * HD;
#pragma unroll
    for (int u = 0; u < 4; u++) {
        int idx = tid + u * 256;
        int t = idx >> 4;
        int d4 = (idx & 15) * 4;
        float w = exp2f((float)(L_CH - t) * lg);
        float4 kv = *(const float4*)(Kg + t * HD + d4);
        kv.x *= w; kv.y *= w; kv.z *= w; kv.w *= w;
        *(float4*)&Ks[t][d4] = kv;
        *(float4*)&Vs[t][d4] = *(const float4*)(Vg + t * HD + d4);
    }
    __syncthreads();

    float acc[4][4];
#pragma unroll
    for (int i = 0; i < 4; i++)
#pragma unroll
        for (int j = 0; j < 4; j++) acc[i][j] = 0.f;

#pragma unroll 4
    for (int k = 0; k < L_CH; k++) {
        float4 ak = *(const float4*)&Ks[k][rB];
        float4 bk = *(const float4*)&Vs[k][cB];
        float ar[4] = {ak.x, ak.y, ak.z, ak.w};
#pragma unroll
        for (int i = 0; i < 4; i++) {
            acc[i][0] += ar[i] * bk.x; acc[i][1] += ar[i] * bk.y;
            acc[i][2] += ar[i] * bk.z; acc[i][3] += ar[i] * bk.w;
        }
    }

    float* Gg = G + ((size_t)bh * NCH + c) * HD * HD;
#pragma unroll
    for (int i = 0; i < 4; i++) {
        float4 v = {acc[i][0], acc[i][1], acc[i][2], acc[i][3]};
        *(float4*)&Gg[(rB + i) * HD + cB] = v;
    }
}

// ---------------------------------------------------------------------------
// Pass B: prefix scan  S_0 = 0 ; S_c = gamma^L * S_{c-1} + G_{c-1}
// grid = BH, 256 threads; each thread owns 16 strided elements of the 64x64 state.
// ---------------------------------------------------------------------------
__global__ __launch_bounds__(256) void state_scan(
    const float* __restrict__ G, float* __restrict__ S)
{
    const int bh = blockIdx.x;
    const int h  = bh & (NH - 1);
    const int tid = threadIdx.x;
    const double g_d = 1.0 - exp2(-5.0 - 0.5 * (double)h);
    const float decL = (float)exp2((double)L_CH * log2(g_d));

    const size_t base = (size_t)bh * NCH * HD * HD;
    float s[16];
#pragma unroll
    for (int u = 0; u < 16; u++) s[u] = 0.f;

    for (int c = 0; c < NCH; c++) {
        const size_t off = base + (size_t)c * HD * HD;
#pragma unroll
        for (int u = 0; u < 16; u++) {
            int e = tid + u * 256;
            S[off + e] = s[u];
            s[u] = s[u] * decL + G[off + e];
        }
    }
}

// ---------------------------------------------------------------------------
// Pass C: O_chunk = gamma^a * (Q/8) @ S_c  +  intra-chunk decayed quadratic
// grid = (NCH, BH), 256 threads. smem: Qs|Kt|Vs|Ss|St = 80KB.
// ---------------------------------------------------------------------------
__global__ __launch_bounds__(256) void retention_chunk(
    const float* __restrict__ Q, const float* __restrict__ K,
    const float* __restrict__ V, const float* __restrict__ S,
    float* __restrict__ O)
{
    extern __shared__ __align__(16) float sm[];
    float* Qs = sm;                  // [t][d] 64x64
    float* Kt = sm + 4096;           // [d][t]
    float* Vs = sm + 8192;           // [t][d]
    float* Ss = sm + 12288;          // [ti][tj]
    float* St = sm + 16384;          // state [d1][d2]

    const int c  = blockIdx.x;
    const int bh = blockIdx.y;
    const int h  = bh & (NH - 1);
    const int r0 = c * L_CH;
    const int tid = threadIdx.x;
    const int rB = (tid >> 4) * 4;
    const int cB = (tid & 15) * 4;

    const double g_d = 1.0 - exp2(-5.0 - 0.5 * (double)h);
    const float lg = (float)log2(g_d);

    const float* Qg = Q + ((size_t)bh * T_SEQ + r0) * HD;
    const float* Kg = K + ((size_t)bh * T_SEQ + r0) * HD;
    const float* Vg = V + ((size_t)bh * T_SEQ + r0) * HD;
    const float* Sg = S + ((size_t)bh * NCH + c) * HD * HD;

#pragma unroll
    for (int u = 0; u < 4; u++) {
        int idx = tid + u * 256;
        int t = idx >> 4;
        int d4 = (idx & 15) * 4;
        *(float4*)&Qs[t * 64 + d4] = *(const float4*)(Qg + t * HD + d4);
        float4 kv = *(const float4*)(Kg + t * HD + d4);
        Kt[(d4 + 0) * 64 + t] = kv.x;
        Kt[(d4 + 1) * 64 + t] = kv.y;
        Kt[(d4 + 2) * 64 + t] = kv.z;
        Kt[(d4 + 3) * 64 + t] = kv.w;
        *(float4*)&Vs[t * 64 + d4] = *(const float4*)(Vg + t * HD + d4);
        *(float4*)&St[t * 64 + d4] = *(const float4*)(Sg + t * HD + d4);
    }
    __syncthreads();

    // cross term: acc = Q @ St  (inner over d1)
    float acc[4][4];
#pragma unroll
    for (int i = 0; i < 4; i++)
#pragma unroll
        for (int j = 0; j < 4; j++) acc[i][j] = 0.f;

#pragma unroll 4
    for (int k = 0; k < HD; k++) {
        float a0 = Qs[(rB + 0) * 64 + k];
        float a1 = Qs[(rB + 1) * 64 + k];
        float a2 = Qs[(rB + 2) * 64 + k];
        float a3 = Qs[(rB + 3) * 64 + k];
        float4 bq = *(const float4*)&St[k * 64 + cB];
        acc[0][0] += a0 * bq.x; acc[0][1] += a0 * bq.y; acc[0][2] += a0 * bq.z; acc[0][3] += a0 * bq.w;
        acc[1][0] += a1 * bq.x; acc[1][1] += a1 * bq.y; acc[1][2] += a1 * bq.z; acc[1][3] += a1 * bq.w;
        acc[2][0] += a2 * bq.x; acc[2][1] += a2 * bq.y; acc[2][2] += a2 * bq.z; acc[2][3] += a2 * bq.w;
        acc[3][0] += a3 * bq.x; acc[3][1] += a3 * bq.y; acc[3][2] += a3 * bq.z; acc[3][3] += a3 * bq.w;
    }
    // scale cross by gamma^a / 8 (a = local row index)
#pragma unroll
    for (int i = 0; i < 4; i++) {
        float f = exp2f((float)(rB + i) * lg) * 0.125f;
#pragma unroll
        for (int j = 0; j < 4; j++) acc[i][j] *= f;
    }

    // intra-chunk: s = Q Kt, decay-mask, Ss
    float s[4][4];
#pragma unroll
    for (int i = 0; i < 4; i++)
#pragma unroll
        for (int j = 0; j < 4; j++) s[i][j] = 0.f;

#pragma unroll 4
    for (int k = 0; k < HD; k++) {
        float a0 = Qs[(rB + 0) * 64 + k];
        float a1 = Qs[(rB + 1) * 64 + k];
        float a2 = Qs[(rB + 2) * 64 + k];
        float a3 = Qs[(rB + 3) * 64 + k];
        float4 bq = *(const float4*)&Kt[k * 64 + cB];
        s[0][0] += a0 * bq.x; s[0][1] += a0 * bq.y; s[0][2] += a0 * bq.z; s[0][3] += a0 * bq.w;
        s[1][0] += a1 * bq.x; s[1][1] += a1 * bq.y; s[1][2] += a1 * bq.z; s[1][3] += a1 * bq.w;
        s[2][0] += a2 * bq.x; s[2][1] += a2 * bq.y; s[2][2] += a2 * bq.z; s[2][3] += a2 * bq.w;
        s[3][0] += a3 * bq.x; s[3][1] += a3 * bq.y; s[3][2] += a3 * bq.z; s[3][3] += a3 * bq.w;
    }

#pragma unroll
    for (int i = 0; i < 4; i++) {
#pragma unroll
        for (int j = 0; j < 4; j++) {
            int di = (rB + i) - (cB + j);
            float dec = (di >= 0) ? exp2f((float)di * lg) : 0.f;
            Ss[(rB + i) * 64 + (cB + j)] = s[i][j] * 0.125f * dec;
        }
    }
    __syncthreads();

    // acc += Ss @ Vs
#pragma unroll 4
    for (int k = 0; k < L_CH; k++) {
        float a0 = Ss[(rB + 0) * 64 + k];
        float a1 = Ss[(rB + 1) * 64 + k];
        float a2 = Ss[(rB + 2) * 64 + k];
        float a3 = Ss[(rB + 3) * 64 + k];
        float4 bv = *(const float4*)&Vs[k * 64 + cB];
        acc[0][0] += a0 * bv.x; acc[0][1] += a0 * bv.y; acc[0][2] += a0 * bv.z; acc[0][3] += a0 * bv.w;
        acc[1][0] += a1 * bv.x; acc[1][1] += a1 * bv.y; acc[1][2] += a1 * bv.z; acc[1][3] += a1 * bv.w;
        acc[2][0] += a2 * bv.x; acc[2][1] += a2 * bv.y; acc[2][2] += a2 * bv.z; acc[2][3] += a2 * bv.w;
        acc[3][0] += a3 * bv.x; acc[3][1] += a3 * bv.y; acc[3][2] += a3 * bv.z; acc[3][3] += a3 * bv.w;
    }

    float* Og = O + ((size_t)bh * T_SEQ + r0) * HD;
#pragma unroll
    for (int i = 0; i < 4; i++) {
        float4 v = {acc[i][0], acc[i][1], acc[i][2], acc[i][3]};
        *(float4*)&Og[(rB + i) * 64 + cB] = v;
    }
}

// ---------------------------------------------------------------------------
// GroupNorm, three stages
// ---------------------------------------------------------------------------
__global__ __launch_bounds__(256) void gn_partial(const float* __restrict__ O)
{
    const int bh   = blockIdx.x >> 4;
    const int slab = blockIdx.x & 15;
    const int tid  = threadIdx.x;
    const float* base = O + (size_t)bh * (T_SEQ * HD) + slab * 8192;

    double s = 0.0, s2 = 0.0;
#pragma unroll
    for (int u = 0; u < 8; u++) {
        float4 v = *(const float4*)(base + (tid + u * 256) * 4);
        s  += (double)v.x + v.y + v.z + v.w;
        s2 += (double)v.x * v.x + (double)v.y * v.y + (double)v.z * v.z + (double)v.w * v.w;
    }
    __shared__ double sh[256], sh2[256];
    sh[tid] = s; sh2[tid] = s2;
    __syncthreads();
    for (int off = 128; off > 0; off >>= 1) {
        if (tid < off) { sh[tid] += sh[tid + off]; sh2[tid] += sh2[tid + off]; }
        __syncthreads();
    }
    if (tid == 0) { g_PS[blockIdx.x] = sh[0]; g_PS2[blockIdx.x] = sh2[0]; }
}

__global__ void gn_finalize()
{
    const int bh = blockIdx.x;
    const int tid = threadIdx.x;   // 32 threads
    double s = 0.0, s2 = 0.0;
    if (tid < 16) { s = g_PS[bh * 16 + tid]; s2 = g_PS2[bh * 16 + tid]; }
#pragma unroll
    for (int off = 8; off > 0; off >>= 1) {
        s  += __shfl_down_sync(0xffffffff, s,  off);
        s2 += __shfl_down_sync(0xffffffff, s2, off);
    }
    if (tid == 0) {
        const double N = (double)(T_SEQ * HD);
        double mu  = s / N;
        double var = s2 / N - mu * mu;
        g_MU[bh] = (float)mu;
        g_RS[bh] = (float)rsqrt(var + 1e-5);
    }
}

__global__ __launch_bounds__(256) void gn_apply(
    const float* __restrict__ O, const float* __restrict__ gw,
    const float* __restrict__ gb, float* __restrict__ Y)
{
    const int f = blockIdx.x * 256 + threadIdx.x;   // float4 index
    const int bh = f >> 15;
    const int rem = f & 32767;
    const int t = rem >> 4;
    const int d4 = (rem & 15) * 4;
    const int b = bh >> 4, h = bh & 15;

    const float mu = g_MU[bh], rs = g_RS[bh];
    float4 v = *(const float4*)(O + ((size_t)bh * T_SEQ + t) * HD + d4);
    float4 w = *(const float4*)(gw + h * HD + d4);
    float4 bb = *(const float4*)(gb + h * HD + d4);
    v.x = (v.x - mu) * rs * w.x + bb.x;
    v.y = (v.y - mu) * rs * w.y + bb.y;
    v.z = (v.z - mu) * rs * w.z + bb.z;
    v.w = (v.w - mu) * rs * w.w + bb.w;
    *(float4*)(Y + ((size_t)b * T_SEQ + t) * DM + h * HD + d4) = v;
}

// ---------------------------------------------------------------------------
extern "C" void kernel_launch(void* const* d_in, const int* in_sizes, int n_in,
                              void* d_out, int out_size)
{
    const float* x   = (const float*)d_in[0];
    const float* Wq  = (const float*)d_in[1];
    const float* Wk  = (const float*)d_in[2];
    const float* Wv  = (const float*)d_in[3];
    const float* Wo  = (const float*)d_in[4];
    const float* gnw = (const float*)d_in[5];
    const float* gnb = (const float*)d_in[6];
    float* out = (float*)d_out;

    float *q, *k, *v, *o, *y, *gg, *ss;
    cudaGetSymbolAddress((void**)&q, g_Q);
    cudaGetSymbolAddress((void**)&k, g_K);
    cudaGetSymbolAddress((void**)&v, g_V);
    cudaGetSymbolAddress((void**)&o, g_O);
    cudaGetSymbolAddress((void**)&y, g_Y);
    cudaGetSymbolAddress((void**)&gg, g_G);
    cudaGetSymbolAddress((void**)&ss, g_S);

    dim3 gB(DM / BN, MROWS / BM);   // (8, 32)
    gemm_nt<<<gB, 256>>>(x, Wq, q, MROWS, DM, DM, 1);
    gemm_nt<<<gB, 256>>>(x, Wk, k, MROWS, DM, DM, 1);
    gemm_nt<<<gB, 256>>>(x, Wv, v, MROWS, DM, DM, 1);

    chunk_state<<<dim3(NCH, BH), 256>>>(k, v, gg);
    state_scan<<<BH, 256>>>(gg, ss);

    cudaFuncSetAttribute(retention_chunk,
                         cudaFuncAttributeMaxDynamicSharedMemorySize, 81920);
    retention_chunk<<<dim3(NCH, BH), 256, 81920>>>(q, k, v, ss, o);

    gn_partial<<<BH * 16, 256>>>(o);
    gn_finalize<<<BH, 32>>>();
    gn_apply<<<(MROWS * DM) / (4 * 256), 256>>>(o, gnw, gnb, y);

    gemm_nt<<<gB, 256>>>(y, Wo, out, MROWS, DM, DM, 0);
}

// round 5
// speedup vs baseline: 3.2214x; 1.8378x over previous
#include <cuda_runtime.h>
#include <cuda_bf16.h>
#include <math.h>

#define T_SEQ   2048
#define NH      16
#define HD      64
#define DM      1024
#define BATCH   2
#define MROWS   (BATCH * T_SEQ)   // 4096
#define L_CH    64
#define NCH     (T_SEQ / L_CH)    // 32
#define BH      (BATCH * NH)      // 32

// ---------------------------------------------------------------------------
// Scratch (device globals: allocation-free per harness rules)
// ---------------------------------------------------------------------------
__device__ __align__(16) float g_Q[(size_t)BH * T_SEQ * HD];
__device__ __align__(16) float g_K[(size_t)BH * T_SEQ * HD];
__device__ __align__(16) float g_V[(size_t)BH * T_SEQ * HD];
__device__ __align__(16) float g_O[(size_t)BH * T_SEQ * HD];
__device__ __align__(16) float g_G[(size_t)BH * NCH * HD * HD];
__device__ __align__(16) float g_S[(size_t)BH * NCH * HD * HD];
__device__ double g_PS[BH * 16];
__device__ double g_PS2[BH * 16];
__device__ float g_MU[BH];
__device__ float g_RS[BH];

__device__ __align__(16) __nv_bfloat16 g_Xhi[(size_t)MROWS * DM];
__device__ __align__(16) __nv_bfloat16 g_Xlo[(size_t)MROWS * DM];
__device__ __align__(16) __nv_bfloat16 g_Whi[4 * (size_t)DM * DM];
__device__ __align__(16) __nv_bfloat16 g_Wlo[4 * (size_t)DM * DM];
__device__ __align__(16) __nv_bfloat16 g_Yhi[(size_t)MROWS * DM];
__device__ __align__(16) __nv_bfloat16 g_Ylo[(size_t)MROWS * DM];

// ---------------------------------------------------------------------------
// Baseline-PTX tensor core helpers (sm_80-class: legal on compute_103)
// ---------------------------------------------------------------------------
__device__ __forceinline__ unsigned smem_u32(const void* p) {
    unsigned a;
    asm("{ .reg .u64 t; cvta.to.shared.u64 t, %1; cvt.u32.u64 %0, t; }"
        : "=r"(a) : "l"(p));
    return a;
}

__device__ __forceinline__ void ldsm_x4(unsigned* r, unsigned addr) {
    asm volatile("ldmatrix.sync.aligned.m8n8.x4.shared.b16 {%0,%1,%2,%3}, [%4];"
                 : "=r"(r[0]), "=r"(r[1]), "=r"(r[2]), "=r"(r[3]) : "r"(addr));
}
__device__ __forceinline__ void ldsm_x2(unsigned* r, unsigned addr) {
    asm volatile("ldmatrix.sync.aligned.m8n8.x2.shared.b16 {%0,%1}, [%2];"
                 : "=r"(r[0]), "=r"(r[1]) : "r"(addr));
}
__device__ __forceinline__ void mma_bf16(float* d, const unsigned* a, const unsigned* b) {
    asm volatile(
        "mma.sync.aligned.m16n8k16.row.col.f32.bf16.bf16.f32 "
        "{%0,%1,%2,%3}, {%4,%5,%6,%7}, {%8,%9}, {%0,%1,%2,%3};"
        : "+f"(d[0]), "+f"(d[1]), "+f"(d[2]), "+f"(d[3])
        : "r"(a[0]), "r"(a[1]), "r"(a[2]), "r"(a[3]), "r"(b[0]), "r"(b[1]));
}

#define CP_ASYNC16(dst, src) \
    asm volatile("cp.async.cg.shared.global [%0], [%1], 16;" :: "r"(dst), "l"(src))
#define CP_COMMIT() asm volatile("cp.async.commit_group;" ::: "memory")
#define CP_WAIT1()  asm volatile("cp.async.wait_group 1;" ::: "memory")
#define CP_WAIT0()  asm volatile("cp.async.wait_group 0;" ::: "memory")

// ---------------------------------------------------------------------------
// fp32 -> (bf16 hi, bf16 lo) split conversion, 8 elems / thread
// ---------------------------------------------------------------------------
__global__ __launch_bounds__(256) void cvt_split(
    const float* __restrict__ X, __nv_bfloat16* __restrict__ hi,
    __nv_bfloat16* __restrict__ lo, int n8)
{
    int i = blockIdx.x * 256 + threadIdx.x;
    if (i >= n8) return;
    float4 a = ((const float4*)X)[2 * i];
    float4 b = ((const float4*)X)[2 * i + 1];
    float v[8] = {a.x, a.y, a.z, a.w, b.x, b.y, b.z, b.w};
    unsigned hu[4], lu[4];
#pragma unroll
    for (int j = 0; j < 4; j++) {
        __nv_bfloat16 h0 = __float2bfloat16(v[2 * j]);
        __nv_bfloat16 h1 = __float2bfloat16(v[2 * j + 1]);
        __nv_bfloat16 l0 = __float2bfloat16(v[2 * j] - __bfloat162float(h0));
        __nv_bfloat16 l1 = __float2bfloat16(v[2 * j + 1] - __bfloat162float(h1));
        hu[j] = (unsigned)__bfloat16_as_ushort(h0) | ((unsigned)__bfloat16_as_ushort(h1) << 16);
        lu[j] = (unsigned)__bfloat16_as_ushort(l0) | ((unsigned)__bfloat16_as_ushort(l1) << 16);
    }
    uint4 hv = {hu[0], hu[1], hu[2], hu[3]};
    uint4 lv = {lu[0], lu[1], lu[2], lu[3]};
    *(uint4*)(hi + (size_t)i * 8) = hv;
    *(uint4*)(lo + (size_t)i * 8) = lv;
}

// ---------------------------------------------------------------------------
// mma.sync GEMM: C[m,n] = sum_k A[m,k]*B[n,k], 3-term bf16 split, fp32 accum.
// Block 128x128, K-chunk 32, cp.async double buffered.
// 8 warps: wm = wid&1 (64 rows), wn = wid>>1 (32 cols).
// layout 0: C row-major MxN.  layout 1: scatter to (B,H,T,D).
// ---------------------------------------------------------------------------
#define KC 32
#define ARS 40                      // padded row stride in bf16 elems (80 B)
#define MATB (128 * ARS * 2)        // 10240 B per matrix tile
#define STGB (4 * MATB)             // 40960 B per stage

__global__ __launch_bounds__(256) void gemm_mma(
    const __nv_bfloat16* __restrict__ Ah, const __nv_bfloat16* __restrict__ Al,
    const __nv_bfloat16* __restrict__ Bh, const __nv_bfloat16* __restrict__ Bl,
    float* __restrict__ C, int M, int N, int K, int layout)
{
    extern __shared__ char smc[];
    const unsigned sb = smem_u32(smc);
    const int tid = threadIdx.x;
    const int wid = tid >> 5;
    const int lane = tid & 31;
    const int bm = blockIdx.y, bn = blockIdx.x;
    const int wm = wid & 1;      // m sub-tile (64 rows)
    const int wn = wid >> 1;     // n sub-tile (32 cols)

    const __nv_bfloat16* gsrc[4] = {
        Ah + (size_t)(bm * 128) * K, Al + (size_t)(bm * 128) * K,
        Bh + (size_t)(bn * 128) * K, Bl + (size_t)(bn * 128) * K };

    // copy one K-chunk (4 matrices x 128 x 32 bf16) into stage s
    auto issue_copy = [&](int c, int s) {
        const unsigned base = sb + s * STGB;
#pragma unroll
        for (int w = 0; w < 4; w++) {
            const __nv_bfloat16* g = gsrc[w] + c * KC;
#pragma unroll
            for (int u = 0; u < 2; u++) {
                int i = tid + u * 256;          // 0..511
                int row = i >> 2;
                int c16 = i & 3;
                unsigned dst = base + w * MATB + row * (ARS * 2) + c16 * 16;
                CP_ASYNC16(dst, g + (size_t)row * K + c16 * 8);
            }
        }
        CP_COMMIT();
    };

    float d[16][4];
#pragma unroll
    for (int f = 0; f < 16; f++)
#pragma unroll
        for (int j = 0; j < 4; j++) d[f][j] = 0.f;

    const int nchunks = K / KC;
    issue_copy(0, 0);

    for (int c = 0; c < nchunks; c++) {
        if (c + 1 < nchunks) {
            issue_copy(c + 1, (c + 1) & 1);
            CP_WAIT1();
        } else {
            CP_WAIT0();
        }
        __syncthreads();

        const unsigned base = sb + (c & 1) * STGB;
#pragma unroll
        for (int kk = 0; kk < KC; kk += 16) {
            unsigned Ahf[4][4], Alf[4][4];
#pragma unroll
            for (int fm = 0; fm < 4; fm++) {
                unsigned row = wm * 64 + fm * 16 + (lane & 15);
                unsigned col = kk + (lane >> 4) * 8;
                unsigned addr = base + row * (ARS * 2) + col * 2;
                ldsm_x4(Ahf[fm], addr);
                ldsm_x4(Alf[fm], addr + MATB);
            }
            unsigned Bhf[4][2], Blf[4][2];
#pragma unroll
            for (int fn = 0; fn < 4; fn++) {
                unsigned row = wn * 32 + fn * 8 + (lane & 7);
                unsigned col = kk + ((lane >> 3) & 1) * 8;
                unsigned addr = base + 2 * MATB + row * (ARS * 2) + col * 2;
                ldsm_x2(Bhf[fn], addr);
                ldsm_x2(Blf[fn], addr + MATB);
            }
#pragma unroll
            for (int fm = 0; fm < 4; fm++)
#pragma unroll
                for (int fn = 0; fn < 4; fn++) {
                    float* acc = d[fm * 4 + fn];
                    mma_bf16(acc, Ahf[fm], Bhf[fn]);
                    mma_bf16(acc, Ahf[fm], Blf[fn]);
                    mma_bf16(acc, Alf[fm], Bhf[fn]);
                }
        }
        __syncthreads();
    }

    // Epilogue
    const int mloc0 = bm * 128 + wm * 64 + (lane >> 2);
    const int nloc0 = bn * 128 + wn * 32 + (lane & 3) * 2;
#pragma unroll
    for (int fm = 0; fm < 4; fm++) {
#pragma unroll
        for (int fn = 0; fn < 4; fn++) {
            const float* acc = d[fm * 4 + fn];
            const int n = nloc0 + fn * 8;
#pragma unroll
            for (int rr = 0; rr < 2; rr++) {
                const int m = mloc0 + fm * 16 + rr * 8;
                float2 v = {acc[rr * 2], acc[rr * 2 + 1]};
                if (layout == 0) {
                    *(float2*)(C + (size_t)m * N + n) = v;
                } else {
                    const int h = n >> 6, dd = n & 63;
                    const int bb = m >> 11, t = m & 2047;
                    *(float2*)(C + (((size_t)(bb * NH + h) * T_SEQ + t) * HD + dd)) = v;
                }
            }
        }
    }
}

// ---------------------------------------------------------------------------
// Pass A: G_c[d1][d2] = sum_b gamma^(L-b) K[b][d1] V[b][d2]
// ---------------------------------------------------------------------------
__global__ __launch_bounds__(256) void chunk_state(
    const float* __restrict__ K, const float* __restrict__ V,
    float* __restrict__ G)
{
    __shared__ __align__(16) float Ks[L_CH][HD];
    __shared__ __align__(16) float Vs[L_CH][HD];

    const int c  = blockIdx.x;
    const int bh = blockIdx.y;
    const int h  = bh & (NH - 1);
    const int tid = threadIdx.x;
    const int rB = (tid >> 4) * 4;
    const int cB = (tid & 15) * 4;

    const double g_d = 1.0 - exp2(-5.0 - 0.5 * (double)h);
    const float lg = (float)log2(g_d);

    const float* Kg = K + ((size_t)bh * T_SEQ + c * L_CH) * HD;
    const float* Vg = V + ((size_t)bh * T_SEQ + c * L_CH) * HD;
#pragma unroll
    for (int u = 0; u < 4; u++) {
        int idx = tid + u * 256;
        int t = idx >> 4;
        int d4 = (idx & 15) * 4;
        float w = exp2f((float)(L_CH - t) * lg);
        float4 kv = *(const float4*)(Kg + t * HD + d4);
        kv.x *= w; kv.y *= w; kv.z *= w; kv.w *= w;
        *(float4*)&Ks[t][d4] = kv;
        *(float4*)&Vs[t][d4] = *(const float4*)(Vg + t * HD + d4);
    }
    __syncthreads();

    float acc[4][4];
#pragma unroll
    for (int i = 0; i < 4; i++)
#pragma unroll
        for (int j = 0; j < 4; j++) acc[i][j] = 0.f;

#pragma unroll 4
    for (int k = 0; k < L_CH; k++) {
        float4 ak = *(const float4*)&Ks[k][rB];
        float4 bk = *(const float4*)&Vs[k][cB];
        float ar[4] = {ak.x, ak.y, ak.z, ak.w};
#pragma unroll
        for (int i = 0; i < 4; i++) {
            acc[i][0] += ar[i] * bk.x; acc[i][1] += ar[i] * bk.y;
            acc[i][2] += ar[i] * bk.z; acc[i][3] += ar[i] * bk.w;
        }
    }

    float* Gg = G + ((size_t)bh * NCH + c) * HD * HD;
#pragma unroll
    for (int i = 0; i < 4; i++) {
        float4 v = {acc[i][0], acc[i][1], acc[i][2], acc[i][3]};
        *(float4*)&Gg[(rB + i) * HD + cB] = v;
    }
}

// ---------------------------------------------------------------------------
// Pass B: S_0 = 0 ; S_c = gamma^L * S_{c-1} + G_{c-1}
// ---------------------------------------------------------------------------
__global__ __launch_bounds__(256) void state_scan(
    const float* __restrict__ G, float* __restrict__ S)
{
    const int bh = blockIdx.x;
    const int h  = bh & (NH - 1);
    const int tid = threadIdx.x;
    const double g_d = 1.0 - exp2(-5.0 - 0.5 * (double)h);
    const float decL = (float)exp2((double)L_CH * log2(g_d));

    const size_t base = (size_t)bh * NCH * HD * HD;
    float s[16];
#pragma unroll
    for (int u = 0; u < 16; u++) s[u] = 0.f;

    for (int c = 0; c < NCH; c++) {
        const size_t off = base + (size_t)c * HD * HD;
#pragma unroll
        for (int u = 0; u < 16; u++) {
            int e = tid + u * 256;
            S[off + e] = s[u];
            s[u] = s[u] * decL + G[off + e];
        }
    }
}

// ---------------------------------------------------------------------------
// Pass C: O = gamma^a * (Q/8) @ S_c + intra-chunk decayed quadratic
// ---------------------------------------------------------------------------
__global__ __launch_bounds__(256) void retention_chunk(
    const float* __restrict__ Q, const float* __restrict__ K,
    const float* __restrict__ V, const float* __restrict__ S,
    float* __restrict__ O)
{
    extern __shared__ __align__(16) float sm[];
    float* Qs = sm;
    float* Kt = sm + 4096;
    float* Vs = sm + 8192;
    float* Ss = sm + 12288;
    float* St = sm + 16384;

    const int c  = blockIdx.x;
    const int bh = blockIdx.y;
    const int h  = bh & (NH - 1);
    const int r0 = c * L_CH;
    const int tid = threadIdx.x;
    const int rB = (tid >> 4) * 4;
    const int cB = (tid & 15) * 4;

    const double g_d = 1.0 - exp2(-5.0 - 0.5 * (double)h);
    const float lg = (float)log2(g_d);

    const float* Qg = Q + ((size_t)bh * T_SEQ + r0) * HD;
    const float* Kg = K + ((size_t)bh * T_SEQ + r0) * HD;
    const float* Vg = V + ((size_t)bh * T_SEQ + r0) * HD;
    const float* Sg = S + ((size_t)bh * NCH + c) * HD * HD;

#pragma unroll
    for (int u = 0; u < 4; u++) {
        int idx = tid + u * 256;
        int t = idx >> 4;
        int d4 = (idx & 15) * 4;
        *(float4*)&Qs[t * 64 + d4] = *(const float4*)(Qg + t * HD + d4);
        float4 kv = *(const float4*)(Kg + t * HD + d4);
        Kt[(d4 + 0) * 64 + t] = kv.x;
        Kt[(d4 + 1) * 64 + t] = kv.y;
        Kt[(d4 + 2) * 64 + t] = kv.z;
        Kt[(d4 + 3) * 64 + t] = kv.w;
        *(float4*)&Vs[t * 64 + d4] = *(const float4*)(Vg + t * HD + d4);
        *(float4*)&St[t * 64 + d4] = *(const float4*)(Sg + t * HD + d4);
    }
    __syncthreads();

    float acc[4][4];
#pragma unroll
    for (int i = 0; i < 4; i++)
#pragma unroll
        for (int j = 0; j < 4; j++) acc[i][j] = 0.f;

#pragma unroll 4
    for (int k = 0; k < HD; k++) {
        float a0 = Qs[(rB + 0) * 64 + k];
        float a1 = Qs[(rB + 1) * 64 + k];
        float a2 = Qs[(rB + 2) * 64 + k];
        float a3 = Qs[(rB + 3) * 64 + k];
        float4 bq = *(const float4*)&St[k * 64 + cB];
        acc[0][0] += a0 * bq.x; acc[0][1] += a0 * bq.y; acc[0][2] += a0 * bq.z; acc[0][3] += a0 * bq.w;
        acc[1][0] += a1 * bq.x; acc[1][1] += a1 * bq.y; acc[1][2] += a1 * bq.z; acc[1][3] += a1 * bq.w;
        acc[2][0] += a2 * bq.x; acc[2][1] += a2 * bq.y; acc[2][2] += a2 * bq.z; acc[2][3] += a2 * bq.w;
        acc[3][0] += a3 * bq.x; acc[3][1] += a3 * bq.y; acc[3][2] += a3 * bq.z; acc[3][3] += a3 * bq.w;
    }
#pragma unroll
    for (int i = 0; i < 4; i++) {
        float f = exp2f((float)(rB + i) * lg) * 0.125f;
#pragma unroll
        for (int j = 0; j < 4; j++) acc[i][j] *= f;
    }

    float s[4][4];
#pragma unroll
    for (int i = 0; i < 4; i++)
#pragma unroll
        for (int j = 0; j < 4; j++) s[i][j] = 0.f;

#pragma unroll 4
    for (int k = 0; k < HD; k++) {
        float a0 = Qs[(rB + 0) * 64 + k];
        float a1 = Qs[(rB + 1) * 64 + k];
        float a2 = Qs[(rB + 2) * 64 + k];
        float a3 = Qs[(rB + 3) * 64 + k];
        float4 bq = *(const float4*)&Kt[k * 64 + cB];
        s[0][0] += a0 * bq.x; s[0][1] += a0 * bq.y; s[0][2] += a0 * bq.z; s[0][3] += a0 * bq.w;
        s[1][0] += a1 * bq.x; s[1][1] += a1 * bq.y; s[1][2] += a1 * bq.z; s[1][3] += a1 * bq.w;
        s[2][0] += a2 * bq.x; s[2][1] += a2 * bq.y; s[2][2] += a2 * bq.z; s[2][3] += a2 * bq.w;
        s[3][0] += a3 * bq.x; s[3][1] += a3 * bq.y; s[3][2] += a3 * bq.z; s[3][3] += a3 * bq.w;
    }

#pragma unroll
    for (int i = 0; i < 4; i++) {
#pragma unroll
        for (int j = 0; j < 4; j++) {
            int di = (rB + i) - (cB + j);
            float dec = (di >= 0) ? exp2f((float)di * lg) : 0.f;
            Ss[(rB + i) * 64 + (cB + j)] = s[i][j] * 0.125f * dec;
        }
    }
    __syncthreads();

#pragma unroll 4
    for (int k = 0; k < L_CH; k++) {
        float a0 = Ss[(rB + 0) * 64 + k];
        float a1 = Ss[(rB + 1) * 64 + k];
        float a2 = Ss[(rB + 2) * 64 + k];
        float a3 = Ss[(rB + 3) * 64 + k];
        float4 bv = *(const float4*)&Vs[k * 64 + cB];
        acc[0][0] += a0 * bv.x; acc[0][1] += a0 * bv.y; acc[0][2] += a0 * bv.z; acc[0][3] += a0 * bv.w;
        acc[1][0] += a1 * bv.x; acc[1][1] += a1 * bv.y; acc[1][2] += a1 * bv.z; acc[1][3] += a1 * bv.w;
        acc[2][0] += a2 * bv.x; acc[2][1] += a2 * bv.y; acc[2][2] += a2 * bv.z; acc[2][3] += a2 * bv.w;
        acc[3][0] += a3 * bv.x; acc[3][1] += a3 * bv.y; acc[3][2] += a3 * bv.z; acc[3][3] += a3 * bv.w;
    }

    float* Og = O + ((size_t)bh * T_SEQ + r0) * HD;
#pragma unroll
    for (int i = 0; i < 4; i++) {
        float4 v = {acc[i][0], acc[i][1], acc[i][2], acc[i][3]};
        *(float4*)&Og[(rB + i) * 64 + cB] = v;
    }
}

// ---------------------------------------------------------------------------
// GroupNorm, three stages (apply emits bf16 hi/lo for the Wo GEMM)
// ---------------------------------------------------------------------------
__global__ __launch_bounds__(256) void gn_partial(const float* __restrict__ O)
{
    const int bh   = blockIdx.x >> 4;
    const int slab = blockIdx.x & 15;
    const int tid  = threadIdx.x;
    const float* base = O + (size_t)bh * (T_SEQ * HD) + slab * 8192;

    double s = 0.0, s2 = 0.0;
#pragma unroll
    for (int u = 0; u < 8; u++) {
        float4 v = *(const float4*)(base + (tid + u * 256) * 4);
        s  += (double)v.x + v.y + v.z + v.w;
        s2 += (double)v.x * v.x + (double)v.y * v.y + (double)v.z * v.z + (double)v.w * v.w;
    }
    __shared__ double sh[256], sh2[256];
    sh[tid] = s; sh2[tid] = s2;
    __syncthreads();
    for (int off = 128; off > 0; off >>= 1) {
        if (tid < off) { sh[tid] += sh[tid + off]; sh2[tid] += sh2[tid + off]; }
        __syncthreads();
    }
    if (tid == 0) { g_PS[blockIdx.x] = sh[0]; g_PS2[blockIdx.x] = sh2[0]; }
}

__global__ void gn_finalize()
{
    const int bh = blockIdx.x;
    const int tid = threadIdx.x;
    double s = 0.0, s2 = 0.0;
    if (tid < 16) { s = g_PS[bh * 16 + tid]; s2 = g_PS2[bh * 16 + tid]; }
#pragma unroll
    for (int off = 8; off > 0; off >>= 1) {
        s  += __shfl_down_sync(0xffffffff, s,  off);
        s2 += __shfl_down_sync(0xffffffff, s2, off);
    }
    if (tid == 0) {
        const double N = (double)(T_SEQ * HD);
        double mu  = s / N;
        double var = s2 / N - mu * mu;
        g_MU[bh] = (float)mu;
        g_RS[bh] = (float)rsqrt(var + 1e-5);
    }
}

__global__ __launch_bounds__(256) void gn_apply(
    const float* __restrict__ O, const float* __restrict__ gw,
    const float* __restrict__ gb, __nv_bfloat16* __restrict__ yhi,
    __nv_bfloat16* __restrict__ ylo)
{
    const int f = blockIdx.x * 256 + threadIdx.x;
    const int bh = f >> 15;
    const int rem = f & 32767;
    const int t = rem >> 4;
    const int d4 = (rem & 15) * 4;
    const int b = bh >> 4, h = bh & 15;

    const float mu = g_MU[bh], rs = g_RS[bh];
    float4 v = *(const float4*)(O + ((size_t)bh * T_SEQ + t) * HD + d4);
    float4 w = *(const float4*)(gw + h * HD + d4);
    float4 bb = *(const float4*)(gb + h * HD + d4);
    float r[4];
    r[0] = (v.x - mu) * rs * w.x + bb.x;
    r[1] = (v.y - mu) * rs * w.y + bb.y;
    r[2] = (v.z - mu) * rs * w.z + bb.z;
    r[3] = (v.w - mu) * rs * w.w + bb.w;

    unsigned hu[2], lu[2];
#pragma unroll
    for (int j = 0; j < 2; j++) {
        __nv_bfloat16 h0 = __float2bfloat16(r[2 * j]);
        __nv_bfloat16 h1 = __float2bfloat16(r[2 * j + 1]);
        __nv_bfloat16 l0 = __float2bfloat16(r[2 * j] - __bfloat162float(h0));
        __nv_bfloat16 l1 = __float2bfloat16(r[2 * j + 1] - __bfloat162float(h1));
        hu[j] = (unsigned)__bfloat16_as_ushort(h0) | ((unsigned)__bfloat16_as_ushort(h1) << 16);
        lu[j] = (unsigned)__bfloat16_as_ushort(l0) | ((unsigned)__bfloat16_as_ushort(l1) << 16);
    }
    const size_t oidx = ((size_t)b * T_SEQ + t) * DM + h * HD + d4;
    uint2 hv = {hu[0], hu[1]};
    uint2 lv = {lu[0], lu[1]};
    *(uint2*)(yhi + oidx) = hv;
    *(uint2*)(ylo + oidx) = lv;
}

// ---------------------------------------------------------------------------
extern "C" void kernel_launch(void* const* d_in, const int* in_sizes, int n_in,
                              void* d_out, int out_size)
{
    const float* x   = (const float*)d_in[0];
    const float* Wq  = (const float*)d_in[1];
    const float* Wk  = (const float*)d_in[2];
    const float* Wv  = (const float*)d_in[3];
    const float* Wo  = (const float*)d_in[4];
    const float* gnw = (const float*)d_in[5];
    const float* gnb = (const float*)d_in[6];
    float* out = (float*)d_out;

    float *q, *k, *v, *o, *gg, *ss;
    __nv_bfloat16 *xh, *xl, *wh, *wl, *yh, *yl;
    cudaGetSymbolAddress((void**)&q, g_Q);
    cudaGetSymbolAddress((void**)&k, g_K);
    cudaGetSymbolAddress((void**)&v, g_V);
    cudaGetSymbolAddress((void**)&o, g_O);
    cudaGetSymbolAddress((void**)&gg, g_G);
    cudaGetSymbolAddress((void**)&ss, g_S);
    cudaGetSymbolAddress((void**)&xh, g_Xhi);
    cudaGetSymbolAddress((void**)&xl, g_Xlo);
    cudaGetSymbolAddress((void**)&wh, g_Whi);
    cudaGetSymbolAddress((void**)&wl, g_Wlo);
    cudaGetSymbolAddress((void**)&yh, g_Yhi);
    cudaGetSymbolAddress((void**)&yl, g_Ylo);

    cudaFuncSetAttribute(gemm_mma, cudaFuncAttributeMaxDynamicSharedMemorySize, 2 * STGB);
    cudaFuncSetAttribute(retention_chunk, cudaFuncAttributeMaxDynamicSharedMemorySize, 81920);

    const int nW = DM * DM / 8;      // 131072
    const int nX = MROWS * DM / 8;   // 524288
    cvt_split<<<(nX + 255) / 256, 256>>>(x, xh, xl, nX);
    cvt_split<<<(nW + 255) / 256, 256>>>(Wq, wh + 0 * (size_t)DM * DM, wl + 0 * (size_t)DM * DM, nW);
    cvt_split<<<(nW + 255) / 256, 256>>>(Wk, wh + 1 * (size_t)DM * DM, wl + 1 * (size_t)DM * DM, nW);
    cvt_split<<<(nW + 255) / 256, 256>>>(Wv, wh + 2 * (size_t)DM * DM, wl + 2 * (size_t)DM * DM, nW);
    cvt_split<<<(nW + 255) / 256, 256>>>(Wo, wh + 3 * (size_t)DM * DM, wl + 3 * (size_t)DM * DM, nW);

    dim3 gB(DM / 128, MROWS / 128);   // (8, 32)
    gemm_mma<<<gB, 256, 2 * STGB>>>(xh, xl, wh + 0 * (size_t)DM * DM, wl + 0 * (size_t)DM * DM, q, MROWS, DM, DM, 1);
    gemm_mma<<<gB, 256, 2 * STGB>>>(xh, xl, wh + 1 * (size_t)DM * DM, wl + 1 * (size_t)DM * DM, k, MROWS, DM, DM, 1);
    gemm_mma<<<gB, 256, 2 * STGB>>>(xh, xl, wh + 2 * (size_t)DM * DM, wl + 2 * (size_t)DM * DM, v, MROWS, DM, DM, 1);

    chunk_state<<<dim3(NCH, BH), 256>>>(k, v, gg);
    state_scan<<<BH, 256>>>(gg, ss);
    retention_chunk<<<dim3(NCH, BH), 256, 81920>>>(q, k, v, ss, o);

    gn_partial<<<BH * 16, 256>>>(o);
    gn_finalize<<<BH, 32>>>();
    gn_apply<<<(MROWS * DM) / (4 * 256), 256>>>(o, gnw, gnb, yh, yl);

    gemm_mma<<<gB, 256, 2 * STGB>>>(yh, yl, wh + 3 * (size_t)DM * DM, wl + 3 * (size_t)DM * DM, out, MROWS, DM, DM, 0);
}